// round 16
// baseline (speedup 1.0000x reference)
#include <cuda_runtime.h>
#include <cuda_bf16.h>
#include <math.h>

// ---------------- problem constants ----------------
#define NB    16
#define NCIN  20
#define NWID  64
#define NPIX  65536      // 256*256
#define NLAY  4
#define M1    16
#define M2    16
#define FCH   128
#define NCOUT 20

typedef unsigned long long ull;
typedef unsigned int uint;

// ---- packed f32x2 helpers ----
__device__ __forceinline__ ull ffma2(ull a, ull b, ull c) {
    ull d; asm("fma.rn.f32x2 %0, %1, %2, %3;" : "=l"(d) : "l"(a), "l"(b), "l"(c)); return d;
}
__device__ __forceinline__ ull add2(ull a, ull b) {
    ull d; asm("add.rn.f32x2 %0, %1, %2;" : "=l"(d) : "l"(a), "l"(b)); return d;
}
__device__ __forceinline__ ull pk2(float lo, float hi) {
    ull r; asm("mov.b64 %0, {%1,%2};" : "=l"(r) : "f"(lo), "f"(hi)); return r;
}
__device__ __forceinline__ float2 up2(ull v) {
    float2 r; asm("mov.b64 {%0,%1}, %2;" : "=f"(r.x), "=f"(r.y) : "l"(v)); return r;
}

// ---- tf32 mma helpers ----
__device__ __forceinline__ uint tf32u(float x) {
    uint y; asm("cvt.rna.tf32.f32 %0, %1;" : "=r"(y) : "f"(x)); return y;
}
#define MMA_TF32(d, a, b) \
    asm volatile("mma.sync.aligned.m16n8k8.row.col.f32.tf32.tf32.f32 " \
                 "{%0,%1,%2,%3}, {%4,%5,%6,%7}, {%8,%9}, {%0,%1,%2,%3};" \
                 : "+f"((d)[0]), "+f"((d)[1]), "+f"((d)[2]), "+f"((d)[3]) \
                 : "r"((a)[0]), "r"((a)[1]), "r"((a)[2]), "r"((a)[3]), \
                   "r"((b)[0]), "r"((b)[1]))

// ---- bf16 pair-split helpers ----
__device__ __forceinline__ uint pkbf(float v) {
    __nv_bfloat16 h = __float2bfloat16_rn(v);
    float hf = __bfloat162float(h);
    __nv_bfloat16 l = __float2bfloat16_rn(v - hf);
    return (uint)__bfloat16_as_ushort(h) | ((uint)__bfloat16_as_ushort(l) << 16);
}
#define MMA_BF16(d, a, b0, b1) \
    asm volatile("mma.sync.aligned.m16n8k16.row.col.f32.bf16.bf16.f32 " \
                 "{%0,%1,%2,%3}, {%4,%5,%6,%7}, {%8,%9}, {%0,%1,%2,%3};" \
                 : "+f"((d)[0]), "+f"((d)[1]), "+f"((d)[2]), "+f"((d)[3]) \
                 : "r"((a)[0]), "r"((a)[1]), "r"((a)[2]), "r"((a)[3]), \
                   "r"(b0), "r"(b1))

__device__ __forceinline__ float gelu_f(float v) {
    return 0.5f * v * (1.f + erff(v * 0.70710678118654752f));
}

// ---------------- device scratch ----------------
__device__ float  g_h0[NB*NWID*NPIX];          // 256 MB ping
__device__ float  g_h1[NB*NWID*NPIX];          // 256 MB pong
__device__ float2 g_T  [NB*256*NWID*16];       // fwd stage1: [b][h][i][ky]  (NEW layout)
__device__ float2 g_Xf [32*16*NB*NWID];        // fwd modes:  [kx][ky][b][i]
__device__ float2 g_Xo [NB*NWID*16*32];        // mixed:      [b][o][ky][kx]
__device__ float2 g_Z  [NB*NWID*256*16];       // inv stage1: [b][o][p][ky]
// twiddle tables
__device__ float g_cw[16*256], g_sw[16*256];   // cos/sin(2*pi*ky*w/256)  [ky][w]
__device__ float g_ch[32*256], g_sh[32*256];   // cos/sin(2*pi*kx*h/256)  [k][h]
// folded DFT-W twiddles (layer-0 standalone dftw), bf16-pair packed
__device__ uint g_E2p[256*16];
// unfolded DFT-W twiddles for fused GEMM2, bf16-pair packed: [w][c], c: 2ky=cos, 2ky+1=-sin
__device__ uint g_E256p[256*32];

// ---------------- table init ----------------
__global__ __launch_bounds__(256) void k_init_tables() {
    int id = blockIdx.x * 256 + threadIdx.x;   // 8192 threads
    if (id < 16*256) {
        int ky = id >> 8, w = id & 255;
        float s, c;
        sincospif((float)(ky * w) * (1.0f/128.0f), &s, &c);
        g_cw[id] = c; g_sw[id] = s;
    }
    if (id < 32*256) {
        int k = id >> 8, h = id & 255;
        int kx = (k < 16) ? k : (224 + k);
        float s, c;
        sincospif((float)(kx * h) * (1.0f/128.0f), &s, &c);
        g_ch[id] = c; g_sh[id] = s;
    }
    if (id < 256*16) {
        int r = id >> 4, c = id & 15;
        int w = r & 127;
        int ky = 2*(c >> 1) + (r >> 7);
        float s, cv;
        sincospif((float)(ky * w) * (1.0f/128.0f), &s, &cv);
        g_E2p[id] = pkbf((c & 1) ? -s : cv);
    }
    {   // g_E256p: all 8192 ids
        int w = id >> 5, c = id & 31;
        int ky = c >> 1;
        float s, cv;
        sincospif((float)(ky * w) * (1.0f/128.0f), &s, &cv);
        g_E256p[id] = pkbf((c & 1) ? -s : cv);
    }
}

// ---------------- lift: h0[b,d,pix] ----------------
__global__ __launch_bounds__(256) void k_fc0(const float* __restrict__ x,
                                             const float* __restrict__ w,
                                             const float* __restrict__ bias) {
    __shared__ float ws[NWID*NCIN];
    __shared__ float bs[NWID];
    int t = threadIdx.x;
    for (int j = t; j < NWID*NCIN; j += 256) ws[j] = w[j];
    if (t < NWID) bs[t] = bias[t];
    __syncthreads();

    int idx = blockIdx.x * 256 + t;
    int b = idx >> 16, pix = idx & 65535;
    ull xin2[10];
#pragma unroll
    for (int q = 0; q < 10; q++) {
        float x0 = x[(size_t)(b*NCIN + 2*q    )*NPIX + pix];
        float x1 = x[(size_t)(b*NCIN + 2*q + 1)*NPIX + pix];
        xin2[q] = pk2(x0, x1);
    }
#pragma unroll 4
    for (int d = 0; d < NWID; d++) {
        const ulonglong2* wp = (const ulonglong2*)(ws + d*NCIN);
        ull a0 = 0ULL, a1 = 0ULL;
#pragma unroll
        for (int q = 0; q < 5; q++) {
            ulonglong2 ww = wp[q];
            a0 = ffma2(xin2[2*q],   ww.x, a0);
            a1 = ffma2(xin2[2*q+1], ww.y, a1);
        }
        float2 u = up2(add2(a0, a1));
        g_h0[(size_t)(b*NWID + d)*NPIX + pix] = u.x + u.y + bs[d];
    }
}

// ---------------- standalone DFT-W (layer 0 only): radix-2 fold + bf16 pair MMA ----
#define DFTW_SMEM ((64*260 + 256*24) * 4)
__global__ __launch_bounds__(256) void k_dftw() {
    const float* __restrict__ hin = g_h0;
    extern __shared__ uint smu[];
    uint* As = smu;               // [row 64][k 256] stride 260 (packed bf16 pairs)
    uint* Bs = smu + 64*260;      // [k 256][n 16] stride 24
    int t = threadIdx.x, lane = t & 31, warp = t >> 5;
    int gr = lane >> 2, gc = lane & 3;

    const float* hsrc = hin + (size_t)blockIdx.x * 64 * 256;
#pragma unroll
    for (int rr = 0; rr < 8; rr++) {
        int r = warp*8 + rr;
        float4 lo = ((const float4*)(hsrc + r*256))[lane];
        float4 hi = ((const float4*)(hsrc + r*256))[lane + 32];
        uint4 p0 = make_uint4(pkbf(lo.x+hi.x), pkbf(lo.y+hi.y), pkbf(lo.z+hi.z), pkbf(lo.w+hi.w));
        uint4 p1 = make_uint4(pkbf(lo.x-hi.x), pkbf(lo.y-hi.y), pkbf(lo.z-hi.z), pkbf(lo.w-hi.w));
        *(uint4*)(As + r*260 +       lane*4) = p0;
        *(uint4*)(As + r*260 + 128 + lane*4) = p1;
    }
#pragma unroll
    for (int rep = 0; rep < 16; rep++) {
        int j = rep*256 + t;
        Bs[(j >> 4)*24 + (j & 15)] = g_E2p[j];
    }
    __syncthreads();

    int grp = warp >> 2;
    int wl  = warp & 3;
    int m0 = (wl & 1) * 32;
    int n0 = (wl >> 1) * 8;
    int kb = grp * 128;

    float acc[2][4] = {};
#pragma unroll
    for (int ks = 0; ks < 16; ks++) {
        int kk = kb + ks*8;
        uint a[2][4];
#pragma unroll
        for (int mi = 0; mi < 2; mi++) {
            int r = m0 + mi*16 + gr;
            a[mi][0] = As[r*260     + kk + gc];
            a[mi][1] = As[(r+8)*260 + kk + gc];
            a[mi][2] = As[r*260     + kk + gc + 4];
            a[mi][3] = As[(r+8)*260 + kk + gc + 4];
        }
        uint b0 = Bs[(kk + gc    )*24 + n0 + gr];
        uint b1 = Bs[(kk + gc + 4)*24 + n0 + gr];
        uint b0s = __byte_perm(b0, b0, 0x1032);
        uint b1s = __byte_perm(b1, b1, 0x1032);
#pragma unroll
        for (int mi = 0; mi < 2; mi++) {
            MMA_BF16(acc[mi], a[mi], b0,  b1);
            MMA_BF16(acc[mi], a[mi], b0s, b1s);
        }
    }

    int bi = blockIdx.x >> 2;
    int b = bi >> 6, i = bi & 63;
    int h0 = (blockIdx.x & 3) * 64;
    int kyi = (n0 >> 1) + gc;
    int ky  = 2*kyi + grp;
#pragma unroll
    for (int mi = 0; mi < 2; mi++)
#pragma unroll
        for (int ep = 0; ep < 2; ep++) {
            int h = h0 + m0 + mi*16 + gr + ep*8;
            g_T[(((size_t)(b*256 + h))*64 + i)*16 + ky] = make_float2(acc[mi][2*ep], acc[mi][2*ep+1]);
        }
}

// ---------------- forward DFT over H: fp32 rotation + radix-2 fold ----------------
// g_T layout: [b][h][i][ky]
__global__ __launch_bounds__(256) void k_dfth() {
    __shared__ float2 Ts[4096];        // even plane [h<128][ky] at 0, odd plane at 2048
    int bi = blockIdx.x;               // b*64 + i (1024 blocks)
    int t = threadIdx.x;
    int b = bi >> 6, i = bi & 63;
    const float2* Tg = g_T + (size_t)b * 256 * 1024 + i*16;
    for (int j = t; j < 2048; j += 256) {
        int h = j >> 4, ky = j & 15;
        float2 u = Tg[(size_t)h*1024 + ky];
        float2 v = Tg[(size_t)(h + 128)*1024 + ky];
        Ts[j]        = make_float2(u.x + v.x, u.y + v.y);
        Ts[2048 + j] = make_float2(u.x - v.x, u.y - v.y);
    }
    __syncthreads();

    int k  = t & 31;                   // 0-15 -> kx=k, 16-31 -> kx=224+k
    int ky = t >> 5;                   // 0..7; also does ky+8
    int pb = (k & 1) ? 2048 : 0;       // parity of kx == parity of k

    float c0 = g_ch[k*256 + 1], s0 = g_sh[k*256 + 1];
    float c = 1.f, s = 0.f;
    float re0 = 0.f, im0 = 0.f, re1 = 0.f, im1 = 0.f;
#pragma unroll 4
    for (int h = 0; h < 128; h++) {
        float2 a  = Ts[pb + h*16 + ky];
        float2 bq = Ts[pb + h*16 + ky + 8];
        re0 = fmaf(a.x,  c, fmaf( a.y,  s, re0));
        im0 = fmaf(a.y,  c, fmaf(-a.x,  s, im0));
        re1 = fmaf(bq.x, c, fmaf( bq.y, s, re1));
        im1 = fmaf(bq.y, c, fmaf(-bq.x, s, im1));
        float cn = fmaf(-s, s0, c*c0);
        float sn = fmaf( c, s0, s*c0);
        c = cn; s = sn;
    }
    g_Xf[((size_t)(k*16 + ky    )*16 + b)*64 + i] = make_float2(re0, im0);
    g_Xf[((size_t)(k*16 + ky + 8)*16 + b)*64 + i] = make_float2(re1, im1);
}

// ---------------- per-mode complex GEMM ----------------
__global__ __launch_bounds__(256) void k_modemix(const float* __restrict__ w1r, const float* __restrict__ w1i,
                                                 const float* __restrict__ w2r, const float* __restrict__ w2i,
                                                 int layer) {
    __shared__ float2 Xs[16*64];
    __shared__ float2 Ws[64*64];
    int mode = blockIdx.x;
    int kx = mode >> 4, ky = mode & 15;
    int t = threadIdx.x;

    const float2* Xg = g_Xf + (size_t)mode * 1024;
    for (int j = t; j < 1024; j += 256) Xs[j] = Xg[j];

    const float* wr; const float* wi; int kxp;
    if (kx < 16) { wr = w1r; wi = w1i; kxp = kx; }
    else         { wr = w2r; wi = w2i; kxp = kx - 16; }
    size_t base = (size_t)layer * (NWID*NWID*256) + (size_t)kxp*16 + ky;
    for (int j = t; j < 4096; j += 256) {
        Ws[j] = make_float2(wr[base + (size_t)j*256], wi[base + (size_t)j*256]);
    }
    __syncthreads();

#pragma unroll
    for (int r = 0; r < 4; r++) {
        int oid = t + 256*r;
        int b = oid >> 6, o = oid & 63;
        float re = 0.f, im = 0.f;
#pragma unroll 8
        for (int i = 0; i < 64; i++) {
            float2 X = Xs[b*64 + i];
            float2 W = Ws[i*64 + o];
            re = fmaf(X.x, W.x, fmaf(-X.y, W.y, re));
            im = fmaf(X.x, W.y, fmaf( X.y, W.x, im));
        }
        g_Xo[((size_t)(b*64 + o)*16 + ky)*32 + kx] = make_float2(re, im);
    }
}

// ---------------- inverse DFT over H ----------------
__global__ __launch_bounds__(256) void k_idfth() {
    __shared__ float2 Xs[16*32];
    int bo = blockIdx.x;
    int t = threadIdx.x;
    {
        const float4* Xg4 = (const float4*)(g_Xo + (size_t)bo * 512);
        float4* Xs4 = (float4*)Xs;
        for (int j = t; j < 256; j += 256) Xs4[j] = Xg4[j];
    }
    __syncthreads();

    float cth[32], sth[32];
#pragma unroll
    for (int k = 0; k < 32; k++) { cth[k] = g_ch[k*256 + t]; sth[k] = g_sh[k*256 + t]; }

    const float scale = 1.0f / 65536.0f;
#pragma unroll 2
    for (int ky = 0; ky < 16; ky++) {
        float re = 0.f, im = 0.f;
#pragma unroll
        for (int k = 0; k < 32; k++) {
            float2 X = Xs[ky*32 + k];
            re = fmaf(X.x, cth[k], fmaf(-X.y, sth[k], re));
            im = fmaf(X.x, sth[k], fmaf( X.y, cth[k], im));
        }
        g_Z[((size_t)bo*256 + t)*16 + ky] = make_float2(re*scale, im*scale);
    }
}

// ---------------- FUSED k_final (layers 0-2): GEMM1 (conv+spec) + GELU + GEMM2 (DFT-W) ----
// Block = (b,p), 512 threads. GEMM1: out[w 256][o 64] = A[w][k96] x B[k][o] (tf32).
// Then hout -> smem bf16-pair; GEMM2: T[o 64][c 32] = hout[o][w256] x E256[w][c] (bf16-pair).
// smem union: phase1 As[96][264] + Bs[96][72]; phase2 Hp[64][260] + E2s[256][40]; pbs tail.
#define KFF_SMEM_BYTES ((96*264 + 96*72 + 64) * 4)
__global__ __launch_bounds__(512) void k_final_fused(int srcsel,
                                                     const float* __restrict__ pw_w,
                                                     const float* __restrict__ pw_b,
                                                     int layer) {
    const float* __restrict__ hin  = srcsel ? g_h1 : g_h0;
    float*       __restrict__ hout = srcsel ? g_h0 : g_h1;

    extern __shared__ uint sm[];
    uint*  As  = sm;                           // [k96][w] stride 264
    uint*  Bs  = sm + 96*264;                  // [k96][o] stride 72
    uint*  Hp  = sm;                           // [o64][w] stride 260 (phase 2)
    uint*  E2s = sm + 64*260;                  // [w256][c] stride 40 (phase 2)
    float* pbs = (float*)(sm + 96*264 + 96*72);

    int t = threadIdx.x;
    int lane = t & 31, warp = t >> 5;          // 16 warps
    int gr = lane >> 2, gc = lane & 3;
    int bx = blockIdx.x;                       // 4096 = b(16) * p(256)
    int b = bx >> 8, p = bx & 255;

    // ---- phase 1 staging ----
    const float* hsrc = hin + (size_t)(b*64)*NPIX + (size_t)p*256;
#pragma unroll
    for (int rr = 0; rr < 4; rr++) {
        int i = warp*4 + rr;
#pragma unroll
        for (int pq = 0; pq < 2; pq++) {
            int w4 = lane + pq*32;
            float4 v = ((const float4*)(hsrc + (size_t)i*NPIX))[w4];
            uint4 uv = make_uint4(tf32u(v.x), tf32u(v.y), tf32u(v.z), tf32u(v.w));
            *(uint4*)(As + i*264 + w4*4) = uv;
        }
    }
#pragma unroll
    for (int rep = 0; rep < 16; rep++) {
        int j = rep*512 + t;                   // 8192 = e(32) * w(256)
        int e = j >> 8, w = j & 255;
        int q = e >> 1;
        float v = (e & 1) ? -g_sw[q*256 + w] : g_cw[q*256 + w];
        As[(64 + e)*264 + w] = tf32u(v);
    }
    const float* pwg = pw_w + (size_t)layer * 4096;
#pragma unroll
    for (int rep = 0; rep < 8; rep++) {
        int j = rep*512 + t;                   // 4096 = o*64 + i
        int o = j >> 6, i = j & 63;
        Bs[i*72 + o] = tf32u(pwg[j]);
    }
#pragma unroll
    for (int rep = 0; rep < 2; rep++) {
        int j = rep*512 + t;                   // 1024 = o*16 + q
        int o = j >> 4, q = j & 15;
        float2 z = g_Z[((size_t)(b*64 + o)*256 + p)*16 + q];
        float a = q ? 2.f : 1.f;
        Bs[(64 + 2*q    )*72 + o] = tf32u(a * z.x);
        Bs[(64 + 2*q + 1)*72 + o] = tf32u(a * z.y);
    }
    if (t < 64) pbs[t] = pw_b[layer*64 + t];
    __syncthreads();

    // ---- GEMM1 mainloop: warp grid 8M x 2N (M=w 256, N=o 64) ----
    int warpM = warp >> 1, warpN = warp & 1;
    int m0 = warpM * 32, n0 = warpN * 32;

    float acc[2][4][4];
#pragma unroll
    for (int mi = 0; mi < 2; mi++)
#pragma unroll
        for (int ni = 0; ni < 4; ni++)
#pragma unroll
            for (int e = 0; e < 4; e++) acc[mi][ni][e] = 0.f;

#pragma unroll
    for (int ks = 0; ks < 12; ks++) {
        int k0 = ks * 8;
        uint a[2][4];
#pragma unroll
        for (int mi = 0; mi < 2; mi++) {
            int r = m0 + mi*16 + gr;
            a[mi][0] = As[(k0 + gc    )*264 + r];
            a[mi][1] = As[(k0 + gc    )*264 + r + 8];
            a[mi][2] = As[(k0 + gc + 4)*264 + r];
            a[mi][3] = As[(k0 + gc + 4)*264 + r + 8];
        }
        uint bf[4][2];
#pragma unroll
        for (int ni = 0; ni < 4; ni++) {
            int n = n0 + ni*8 + gr;
            bf[ni][0] = Bs[(k0 + gc    )*72 + n];
            bf[ni][1] = Bs[(k0 + gc + 4)*72 + n];
        }
#pragma unroll
        for (int mi = 0; mi < 2; mi++)
#pragma unroll
            for (int ni = 0; ni < 4; ni++)
                MMA_TF32(acc[mi][ni], a[mi], bf[ni]);
    }

    __syncthreads();   // As/Bs dead; safe to overwrite with Hp/E2s

    // ---- epilogue 1: bias + GELU -> gmem hout AND smem bf16-pair Hp[o][w] ----
    size_t outbase = (size_t)(b*64)*NPIX + (size_t)p*256;
#pragma unroll
    for (int mi = 0; mi < 2; mi++)
#pragma unroll
        for (int ni = 0; ni < 4; ni++)
#pragma unroll
            for (int e = 0; e < 4; e++) {
                int row = m0 + mi*16 + gr + (e >> 1)*8;      // w
                int col = n0 + ni*8 + 2*gc + (e & 1);        // o
                float val = gelu_f(acc[mi][ni][e] + pbs[col]);
                hout[outbase + (size_t)col*NPIX + row] = val;
                Hp[col*260 + row] = pkbf(val);
            }
    // stage E256p
#pragma unroll
    for (int rep = 0; rep < 16; rep++) {
        int j = rep*512 + t;                   // 8192 = w(256) * c(32)
        int w = j >> 5, c = j & 31;
        E2s[w*40 + c] = g_E256p[j];
    }
    __syncthreads();

    // ---- GEMM2: T[o][c] = Hp[o][w] x E2s[w][c], bf16 pair-split ----
    int warpM2 = warp & 3, warpN2 = warp >> 2;
    int m0b = warpM2 * 16, n0b = warpN2 * 8;

    float acc2[4] = {};
#pragma unroll
    for (int ks = 0; ks < 32; ks++) {
        int k0 = ks * 8;
        uint a[4];
        a[0] = Hp[(m0b + gr    )*260 + k0 + gc];
        a[1] = Hp[(m0b + gr + 8)*260 + k0 + gc];
        a[2] = Hp[(m0b + gr    )*260 + k0 + gc + 4];
        a[3] = Hp[(m0b + gr + 8)*260 + k0 + gc + 4];
        uint b0 = E2s[(k0 + gc    )*40 + n0b + gr];
        uint b1 = E2s[(k0 + gc + 4)*40 + n0b + gr];
        uint b0s = __byte_perm(b0, b0, 0x1032);
        uint b1s = __byte_perm(b1, b1, 0x1032);
        MMA_BF16(acc2, a, b0,  b1);
        MMA_BF16(acc2, a, b0s, b1s);
    }

    // epilogue 2: cols (2ky, 2ky+1) = (Tr, Ti); write g_T[b][p][o][ky]
    int ky = (n0b >> 1) + gc;
    float2* Tg = g_T + ((size_t)(b*256 + p))*1024;   // [o][ky] block, 1024 float2
#pragma unroll
    for (int ep = 0; ep < 2; ep++) {
        int o = m0b + gr + ep*8;
        Tg[o*16 + ky] = make_float2(acc2[2*ep], acc2[2*ep+1]);
    }
}

// ---------------- plain k_final (layer 3, no gelu, no T) ----------------
#define KF_SMEM_BYTES ((96*136 + 96*72 + 64) * 4)
__global__ __launch_bounds__(256) void k_final(int srcsel,
                                               const float* __restrict__ pw_w,
                                               const float* __restrict__ pw_b,
                                               int layer) {
    const float* __restrict__ hin  = srcsel ? g_h1 : g_h0;
    float*       __restrict__ hout = srcsel ? g_h0 : g_h1;

    extern __shared__ uint smem_u[];
    uint*  As  = smem_u;                       // [k][w] stride 136
    uint*  Bs  = smem_u + 96*136;              // [k][o] stride 72
    float* pbs = (float*)(smem_u + 96*136 + 96*72);

    int t = threadIdx.x;
    int lane = t & 31, warp = t >> 5;
    int bx = blockIdx.x;                       // 8192
    int b = bx >> 9, p = (bx >> 1) & 255, half = bx & 1;
    int w0 = half * 128;

    const float* hsrc = hin + (size_t)(b*64)*NPIX + (size_t)p*256 + w0;
#pragma unroll
    for (int rr = 0; rr < 8; rr++) {
        int i = warp*8 + rr;
        float4 v = *(const float4*)(hsrc + (size_t)i*NPIX + lane*4);
        uint4 uv = make_uint4(tf32u(v.x), tf32u(v.y), tf32u(v.z), tf32u(v.w));
        *(uint4*)(As + i*136 + lane*4) = uv;
    }
#pragma unroll
    for (int rep = 0; rep < 16; rep++) {
        int j = rep*256 + t;
        int e = j >> 7, w = j & 127;
        int q = e >> 1;
        float v = (e & 1) ? -g_sw[q*256 + w0 + w] : g_cw[q*256 + w0 + w];
        As[(64 + e)*136 + w] = tf32u(v);
    }
    const float* pwg = pw_w + (size_t)layer * 4096;
#pragma unroll
    for (int rep = 0; rep < 16; rep++) {
        int j = rep*256 + t;
        int o = j >> 6, i = j & 63;
        Bs[i*72 + o] = tf32u(pwg[j]);
    }
#pragma unroll
    for (int rep = 0; rep < 4; rep++) {
        int j = rep*256 + t;
        int o = j >> 4, q = j & 15;
        float2 z = g_Z[((size_t)(b*64 + o)*256 + p)*16 + q];
        float a = q ? 2.f : 1.f;
        Bs[(64 + 2*q    )*72 + o] = tf32u(a * z.x);
        Bs[(64 + 2*q + 1)*72 + o] = tf32u(a * z.y);
    }
    if (t < 64) pbs[t] = pw_b[layer*64 + t];
    __syncthreads();

    int warpM = warp & 3, warpN = warp >> 2;
    int m0 = warpM * 32, n0 = warpN * 32;
    int gr = lane >> 2, gc = lane & 3;

    float acc[2][4][4];
#pragma unroll
    for (int mi = 0; mi < 2; mi++)
#pragma unroll
        for (int ni = 0; ni < 4; ni++)
#pragma unroll
            for (int e = 0; e < 4; e++) acc[mi][ni][e] = 0.f;

#pragma unroll
    for (int ks = 0; ks < 12; ks++) {
        int k0 = ks * 8;
        uint a[2][4];
#pragma unroll
        for (int mi = 0; mi < 2; mi++) {
            int r = m0 + mi*16 + gr;
            a[mi][0] = As[(k0 + gc    )*136 + r];
            a[mi][1] = As[(k0 + gc    )*136 + r + 8];
            a[mi][2] = As[(k0 + gc + 4)*136 + r];
            a[mi][3] = As[(k0 + gc + 4)*136 + r + 8];
        }
        uint bf[4][2];
#pragma unroll
        for (int ni = 0; ni < 4; ni++) {
            int n = n0 + ni*8 + gr;
            bf[ni][0] = Bs[(k0 + gc    )*72 + n];
            bf[ni][1] = Bs[(k0 + gc + 4)*72 + n];
        }
#pragma unroll
        for (int mi = 0; mi < 2; mi++)
#pragma unroll
            for (int ni = 0; ni < 4; ni++)
                MMA_TF32(acc[mi][ni], a[mi], bf[ni]);
    }

    size_t outbase = (size_t)(b*64)*NPIX + (size_t)p*256 + w0;
#pragma unroll
    for (int mi = 0; mi < 2; mi++)
#pragma unroll
        for (int ni = 0; ni < 4; ni++)
#pragma unroll
            for (int e = 0; e < 4; e++) {
                int row = m0 + mi*16 + gr + (e >> 1)*8;
                int col = n0 + ni*8 + 2*gc + (e & 1);
                hout[outbase + (size_t)col*NPIX + row] = acc[mi][ni][e] + pbs[col];
            }
}

// ---------------- fc1+GELU+fc2 as tf32 MMA ----------------
#define KFC_SMEM_BYTES ((128*136 + 128*40 + 128 + 32) * 4)
__global__ __launch_bounds__(256) void k_fc12(float* __restrict__ out,
                                              const float* __restrict__ fc1w, const float* __restrict__ fc1b,
                                              const float* __restrict__ fc2w, const float* __restrict__ fc2b) {
    extern __shared__ uint smem_u[];
    uint*  As  = smem_u;
    uint*  Bs1 = smem_u + 64*136;
    uint*  Hs  = smem_u;
    uint*  Bs2 = smem_u + 128*136;
    float* b1s = (float*)(smem_u + 128*136 + 128*40);
    float* b2s = b1s + 128;

    int t = threadIdx.x;
    int lane = t & 31, warp = t >> 5;
    int bx = blockIdx.x;
    int b = bx >> 9, p = (bx >> 1) & 255, half = bx & 1;
    int w0 = half * 128;

    const float* hsrc = g_h0 + (size_t)(b*64)*NPIX + (size_t)p*256 + w0;
#pragma unroll
    for (int rr = 0; rr < 8; rr++) {
        int i = warp*8 + rr;
        float4 v = *(const float4*)(hsrc + (size_t)i*NPIX + lane*4);
        uint4 uv = make_uint4(tf32u(v.x), tf32u(v.y), tf32u(v.z), tf32u(v.w));
        *(uint4*)(As + i*136 + lane*4) = uv;
    }
#pragma unroll
    for (int rep = 0; rep < 32; rep++) {
        int j2 = rep*256 + t;
        int jj = j2 >> 6, i = j2 & 63;
        Bs1[i*136 + jj] = tf32u(fc1w[j2]);
    }
#pragma unroll
    for (int rep = 0; rep < 12; rep++) {
        int j2 = rep*256 + t;
        int jj = j2 / 24, o = j2 - jj*24;
        float v = (o < 20) ? fc2w[o*FCH + jj] : 0.f;
        Bs2[jj*40 + o] = tf32u(v);
    }
    if (t < FCH)   b1s[t] = fc1b[t];
    if (t < NCOUT) b2s[t] = fc2b[t];
    __syncthreads();

    int gr = lane >> 2, gc = lane & 3;

    int warpM = warp & 1, warpN = warp >> 1;
    int m0 = warpM * 64, n0 = warpN * 32;
    float acc1[4][4][4];
#pragma unroll
    for (int mi = 0; mi < 4; mi++)
#pragma unroll
        for (int ni = 0; ni < 4; ni++)
#pragma unroll
            for (int e = 0; e < 4; e++) acc1[mi][ni][e] = 0.f;

#pragma unroll
    for (int ks = 0; ks < 8; ks++) {
        int k0 = ks * 8;
        uint a[4][4];
#pragma unroll
        for (int mi = 0; mi < 4; mi++) {
            int r = m0 + mi*16 + gr;
            a[mi][0] = As[(k0 + gc    )*136 + r];
            a[mi][1] = As[(k0 + gc    )*136 + r + 8];
            a[mi][2] = As[(k0 + gc + 4)*136 + r];
            a[mi][3] = As[(k0 + gc + 4)*136 + r + 8];
        }
        uint bf[4][2];
#pragma unroll
        for (int ni = 0; ni < 4; ni++) {
            int n = n0 + ni*8 + gr;
            bf[ni][0] = Bs1[(k0 + gc    )*136 + n];
            bf[ni][1] = Bs1[(k0 + gc + 4)*136 + n];
        }
#pragma unroll
        for (int mi = 0; mi < 4; mi++)
#pragma unroll
            for (int ni = 0; ni < 4; ni++)
                MMA_TF32(acc1[mi][ni], a[mi], bf[ni]);
    }

    __syncthreads();

#pragma unroll
    for (int mi = 0; mi < 4; mi++)
#pragma unroll
        for (int ni = 0; ni < 4; ni++)
#pragma unroll
            for (int e = 0; e < 4; e++) {
                int row = m0 + mi*16 + gr + (e >> 1)*8;
                int col = n0 + ni*8 + 2*gc + (e & 1);
                float v = gelu_f(acc1[mi][ni][e] + b1s[col]);
                Hs[col*136 + row] = tf32u(v);
            }
    __syncthreads();

    int m0b = warp * 16;
    float acc2[3][4];
#pragma unroll
    for (int ni = 0; ni < 3; ni++)
#pragma unroll
        for (int e = 0; e < 4; e++) acc2[ni][e] = 0.f;

#pragma unroll
    for (int ks = 0; ks < 16; ks++) {
        int k0 = ks * 8;
        uint a[4];
        {
            int r = m0b + gr;
            a[0] = Hs[(k0 + gc    )*136 + r];
            a[1] = Hs[(k0 + gc    )*136 + r + 8];
            a[2] = Hs[(k0 + gc + 4)*136 + r];
            a[3] = Hs[(k0 + gc + 4)*136 + r + 8];
        }
        uint bf[3][2];
#pragma unroll
        for (int ni = 0; ni < 3; ni++) {
            int n = ni*8 + gr;
            bf[ni][0] = Bs2[(k0 + gc    )*40 + n];
            bf[ni][1] = Bs2[(k0 + gc + 4)*40 + n];
        }
#pragma unroll
        for (int ni = 0; ni < 3; ni++)
            MMA_TF32(acc2[ni], a, bf[ni]);
    }

    size_t outbase = (size_t)(b*NCOUT)*NPIX + (size_t)p*256 + w0;
#pragma unroll
    for (int ni = 0; ni < 3; ni++)
#pragma unroll
        for (int e = 0; e < 4; e++) {
            int row = m0b + gr + (e >> 1)*8;
            int col = ni*8 + 2*gc + (e & 1);
            if (col < NCOUT)
                out[outbase + (size_t)col*NPIX + row] = acc2[ni][e] + b2s[col];
        }
}

// ---------------- launch ----------------
extern "C" void kernel_launch(void* const* d_in, const int* in_sizes, int n_in,
                              void* d_out, int out_size) {
    const float* x    = (const float*)d_in[0];
    const float* w1r  = (const float*)d_in[1];
    const float* w1i  = (const float*)d_in[2];
    const float* w2r  = (const float*)d_in[3];
    const float* w2i  = (const float*)d_in[4];
    const float* pw_w = (const float*)d_in[5];
    const float* pw_b = (const float*)d_in[6];
    const float* fc0w = (const float*)d_in[7];
    const float* fc0b = (const float*)d_in[8];
    const float* fc1w = (const float*)d_in[9];
    const float* fc1b = (const float*)d_in[10];
    const float* fc2w = (const float*)d_in[11];
    const float* fc2b = (const float*)d_in[12];
    float* out = (float*)d_out;

    cudaFuncSetAttribute(k_final_fused, cudaFuncAttributeMaxDynamicSharedMemorySize, KFF_SMEM_BYTES);
    cudaFuncSetAttribute(k_final, cudaFuncAttributeMaxDynamicSharedMemorySize, KF_SMEM_BYTES);
    cudaFuncSetAttribute(k_fc12,  cudaFuncAttributeMaxDynamicSharedMemorySize, KFC_SMEM_BYTES);
    cudaFuncSetAttribute(k_dftw,  cudaFuncAttributeMaxDynamicSharedMemorySize, DFTW_SMEM);

    k_init_tables<<<32, 256>>>();
    k_fc0<<<4096, 256>>>(x, fc0w, fc0b);
    k_dftw<<<4096, 256, DFTW_SMEM>>>();        // layer 0 only: h0 -> T

    for (int l = 0; l < 3; l++) {
        int src = l & 1;                       // 0: read h0/write h1; 1: reverse
        k_dfth<<<1024, 256>>>();
        k_modemix<<<512, 256>>>(w1r, w1i, w2r, w2i, l);
        k_idfth<<<1024, 256>>>();
        k_final_fused<<<4096, 512, KFF_SMEM_BYTES>>>(src, pw_w, pw_b, l);  // writes h + T for l+1
    }
    // layer 3: plain (no gelu, no T)
    k_dfth<<<1024, 256>>>();
    k_modemix<<<512, 256>>>(w1r, w1i, w2r, w2i, 3);
    k_idfth<<<1024, 256>>>();
    k_final<<<8192, 256, KF_SMEM_BYTES>>>(1, pw_w, pw_b, 3);   // h1 -> h0

    k_fc12<<<8192, 256, KFC_SMEM_BYTES>>>(out, fc1w, fc1b, fc2w, fc2b);
}

// round 17
// speedup vs baseline: 1.0562x; 1.0562x over previous
#include <cuda_runtime.h>
#include <cuda_bf16.h>
#include <math.h>

// ---------------- problem constants ----------------
#define NB    16
#define NCIN  20
#define NWID  64
#define NPIX  65536      // 256*256
#define NLAY  4
#define M1    16
#define M2    16
#define FCH   128
#define NCOUT 20

typedef unsigned long long ull;
typedef unsigned int uint;

// ---- packed f32x2 helpers ----
__device__ __forceinline__ ull ffma2(ull a, ull b, ull c) {
    ull d; asm("fma.rn.f32x2 %0, %1, %2, %3;" : "=l"(d) : "l"(a), "l"(b), "l"(c)); return d;
}
__device__ __forceinline__ ull add2(ull a, ull b) {
    ull d; asm("add.rn.f32x2 %0, %1, %2;" : "=l"(d) : "l"(a), "l"(b)); return d;
}
__device__ __forceinline__ ull pk2(float lo, float hi) {
    ull r; asm("mov.b64 %0, {%1,%2};" : "=l"(r) : "f"(lo), "f"(hi)); return r;
}
__device__ __forceinline__ float2 up2(ull v) {
    float2 r; asm("mov.b64 {%0,%1}, %2;" : "=f"(r.x), "=f"(r.y) : "l"(v)); return r;
}

// ---- tf32 mma helpers ----
__device__ __forceinline__ uint tf32u(float x) {
    uint y; asm("cvt.rna.tf32.f32 %0, %1;" : "=r"(y) : "f"(x)); return y;
}
#define MMA_TF32(d, a, b) \
    asm volatile("mma.sync.aligned.m16n8k8.row.col.f32.tf32.tf32.f32 " \
                 "{%0,%1,%2,%3}, {%4,%5,%6,%7}, {%8,%9}, {%0,%1,%2,%3};" \
                 : "+f"((d)[0]), "+f"((d)[1]), "+f"((d)[2]), "+f"((d)[3]) \
                 : "r"((a)[0]), "r"((a)[1]), "r"((a)[2]), "r"((a)[3]), \
                   "r"((b)[0]), "r"((b)[1]))

// ---- bf16 pair-split helpers ----
__device__ __forceinline__ uint pkbf(float v) {
    __nv_bfloat16 h = __float2bfloat16_rn(v);
    float hf = __bfloat162float(h);
    __nv_bfloat16 l = __float2bfloat16_rn(v - hf);
    return (uint)__bfloat16_as_ushort(h) | ((uint)__bfloat16_as_ushort(l) << 16);
}
#define MMA_BF16(d, a, b0, b1) \
    asm volatile("mma.sync.aligned.m16n8k16.row.col.f32.bf16.bf16.f32 " \
                 "{%0,%1,%2,%3}, {%4,%5,%6,%7}, {%8,%9}, {%0,%1,%2,%3};" \
                 : "+f"((d)[0]), "+f"((d)[1]), "+f"((d)[2]), "+f"((d)[3]) \
                 : "r"((a)[0]), "r"((a)[1]), "r"((a)[2]), "r"((a)[3]), \
                   "r"(b0), "r"(b1))

__device__ __forceinline__ float gelu_f(float v) {
    return 0.5f * v * (1.f + erff(v * 0.70710678118654752f));
}

// ---------------- device scratch ----------------
__device__ float  g_h0[NB*NWID*NPIX];          // 256 MB ping
__device__ float  g_h1[NB*NWID*NPIX];          // 256 MB pong
__device__ float2 g_T  [NB*NWID*16*256];       // fwd stage1: [b][i][ky][h]
__device__ float2 g_Xf [32*16*NB*NWID];        // fwd modes:  [kx][ky][b][i]
__device__ float2 g_Xo [NB*NWID*16*32];        // mixed:      [b][o][ky][kx]
__device__ float2 g_Z  [NB*NWID*256*16];       // inv stage1: [b][o][p][ky]
// twiddle tables
__device__ float g_cw[16*256], g_sw[16*256];   // cos/sin(2*pi*ky*w/256)  [ky][w]
__device__ float g_ch[32*256], g_sh[32*256];   // cos/sin(2*pi*kx*h/256)  [k][h]
// folded DFT-W twiddles, bf16-pair packed
__device__ uint g_E2p[256*16];

// ---------------- table init ----------------
__global__ __launch_bounds__(256) void k_init_tables() {
    int id = blockIdx.x * 256 + threadIdx.x;   // 8192 threads
    if (id < 16*256) {
        int ky = id >> 8, w = id & 255;
        float s, c;
        sincospif((float)(ky * w) * (1.0f/128.0f), &s, &c);
        g_cw[id] = c; g_sw[id] = s;
    }
    if (id < 32*256) {
        int k = id >> 8, h = id & 255;
        int kx = (k < 16) ? k : (224 + k);
        float s, c;
        sincospif((float)(kx * h) * (1.0f/128.0f), &s, &c);
        g_ch[id] = c; g_sh[id] = s;
    }
    if (id < 256*16) {
        int r = id >> 4, c = id & 15;
        int w = r & 127;
        int ky = 2*(c >> 1) + (r >> 7);
        float s, cv;
        sincospif((float)(ky * w) * (1.0f/128.0f), &s, &cv);
        g_E2p[id] = pkbf((c & 1) ? -s : cv);
    }
}

// ---------------- lift: h0[b,d,pix] ----------------
__global__ __launch_bounds__(256) void k_fc0(const float* __restrict__ x,
                                             const float* __restrict__ w,
                                             const float* __restrict__ bias) {
    __shared__ float ws[NWID*NCIN];
    __shared__ float bs[NWID];
    int t = threadIdx.x;
    for (int j = t; j < NWID*NCIN; j += 256) ws[j] = w[j];
    if (t < NWID) bs[t] = bias[t];
    __syncthreads();

    int idx = blockIdx.x * 256 + t;
    int b = idx >> 16, pix = idx & 65535;
    ull xin2[10];
#pragma unroll
    for (int q = 0; q < 10; q++) {
        float x0 = x[(size_t)(b*NCIN + 2*q    )*NPIX + pix];
        float x1 = x[(size_t)(b*NCIN + 2*q + 1)*NPIX + pix];
        xin2[q] = pk2(x0, x1);
    }
#pragma unroll 4
    for (int d = 0; d < NWID; d++) {
        const ulonglong2* wp = (const ulonglong2*)(ws + d*NCIN);
        ull a0 = 0ULL, a1 = 0ULL;
#pragma unroll
        for (int q = 0; q < 5; q++) {
            ulonglong2 ww = wp[q];
            a0 = ffma2(xin2[2*q],   ww.x, a0);
            a1 = ffma2(xin2[2*q+1], ww.y, a1);
        }
        float2 u = up2(add2(a0, a1));
        g_h0[(size_t)(b*NWID + d)*NPIX + pix] = u.x + u.y + bs[d];
    }
}

// ---------------- DFT over W: radix-2 fold + bf16 pair MMA ----------------
#define DFTW_SMEM ((64*260 + 256*24) * 4)
__global__ __launch_bounds__(256) void k_dftw(int srcsel) {
    const float* __restrict__ hin = srcsel ? g_h1 : g_h0;
    extern __shared__ uint smu[];
    uint* As = smu;               // [row 64][k 256] stride 260 (packed bf16 pairs)
    uint* Bs = smu + 64*260;      // [k 256][n 16] stride 24
    int t = threadIdx.x, lane = t & 31, warp = t >> 5;
    int gr = lane >> 2, gc = lane & 3;

    const float* hsrc = hin + (size_t)blockIdx.x * 64 * 256;
#pragma unroll
    for (int rr = 0; rr < 8; rr++) {
        int r = warp*8 + rr;
        float4 lo = ((const float4*)(hsrc + r*256))[lane];
        float4 hi = ((const float4*)(hsrc + r*256))[lane + 32];
        uint4 p0 = make_uint4(pkbf(lo.x+hi.x), pkbf(lo.y+hi.y), pkbf(lo.z+hi.z), pkbf(lo.w+hi.w));
        uint4 p1 = make_uint4(pkbf(lo.x-hi.x), pkbf(lo.y-hi.y), pkbf(lo.z-hi.z), pkbf(lo.w-hi.w));
        *(uint4*)(As + r*260 +       lane*4) = p0;
        *(uint4*)(As + r*260 + 128 + lane*4) = p1;
    }
#pragma unroll
    for (int rep = 0; rep < 16; rep++) {
        int j = rep*256 + t;
        Bs[(j >> 4)*24 + (j & 15)] = g_E2p[j];
    }
    __syncthreads();

    int grp = warp >> 2;
    int wl  = warp & 3;
    int m0 = (wl & 1) * 32;
    int n0 = (wl >> 1) * 8;
    int kb = grp * 128;

    float acc[2][4] = {};
#pragma unroll
    for (int ks = 0; ks < 16; ks++) {
        int kk = kb + ks*8;
        uint a[2][4];
#pragma unroll
        for (int mi = 0; mi < 2; mi++) {
            int r = m0 + mi*16 + gr;
            a[mi][0] = As[r*260     + kk + gc];
            a[mi][1] = As[(r+8)*260 + kk + gc];
            a[mi][2] = As[r*260     + kk + gc + 4];
            a[mi][3] = As[(r+8)*260 + kk + gc + 4];
        }
        uint b0 = Bs[(kk + gc    )*24 + n0 + gr];
        uint b1 = Bs[(kk + gc + 4)*24 + n0 + gr];
        uint b0s = __byte_perm(b0, b0, 0x1032);
        uint b1s = __byte_perm(b1, b1, 0x1032);
#pragma unroll
        for (int mi = 0; mi < 2; mi++) {
            MMA_BF16(acc[mi], a[mi], b0,  b1);
            MMA_BF16(acc[mi], a[mi], b0s, b1s);
        }
    }

    int bi = blockIdx.x >> 2;
    int h0 = (blockIdx.x & 3) * 64;
    int kyi = (n0 >> 1) + gc;
    int ky  = 2*kyi + grp;
    float2* Tg = g_T + (size_t)bi*4096 + ky*256;
#pragma unroll
    for (int mi = 0; mi < 2; mi++)
#pragma unroll
        for (int ep = 0; ep < 2; ep++) {
            int h = h0 + m0 + mi*16 + gr + ep*8;
            Tg[h] = make_float2(acc[mi][2*ep], acc[mi][2*ep+1]);
        }
}

// ---------------- forward DFT over H: fp32 rotation + radix-2 fold ----------------
__global__ __launch_bounds__(256) void k_dfth() {
    __shared__ float2 Ts[2*2048 + 4];   // even plane at 0, odd plane at 2052
    int bi = blockIdx.x;                // b*64 + i (1024 blocks)
    int t = threadIdx.x;
    const float2* Tg = g_T + (size_t)bi * 4096;
    for (int j = t; j < 2048; j += 256) {
        int ky = j >> 7, h = j & 127;
        float2 u = Tg[ky*256 + h];
        float2 v = Tg[ky*256 + h + 128];
        Ts[j]        = make_float2(u.x + v.x, u.y + v.y);
        Ts[2052 + j] = make_float2(u.x - v.x, u.y - v.y);
    }
    __syncthreads();

    int k  = t & 31;                    // 0-15 -> kx=k, 16-31 -> kx=224+k
    int ky = t >> 5;                    // 0..7; also ky+8
    int b = bi >> 6, i = bi & 63;
    int pb = (k & 1) ? 2052 : 0;

    float c0 = g_ch[k*256 + 1], s0 = g_sh[k*256 + 1];
    float c = 1.f, s = 0.f;
    float re0 = 0.f, im0 = 0.f, re1 = 0.f, im1 = 0.f;
#pragma unroll 4
    for (int h = 0; h < 128; h++) {
        float2 a  = Ts[pb + ky*128 + h];
        float2 bq = Ts[pb + (ky + 8)*128 + h];
        re0 = fmaf(a.x,  c, fmaf( a.y,  s, re0));
        im0 = fmaf(a.y,  c, fmaf(-a.x,  s, im0));
        re1 = fmaf(bq.x, c, fmaf( bq.y, s, re1));
        im1 = fmaf(bq.y, c, fmaf(-bq.x, s, im1));
        float cn = fmaf(-s, s0, c*c0);
        float sn = fmaf( c, s0, s*c0);
        c = cn; s = sn;
    }
    g_Xf[((size_t)(k*16 + ky    )*16 + b)*64 + i] = make_float2(re0, im0);
    g_Xf[((size_t)(k*16 + ky + 8)*16 + b)*64 + i] = make_float2(re1, im1);
}

// ---------------- per-mode complex GEMM ----------------
__global__ __launch_bounds__(256) void k_modemix(const float* __restrict__ w1r, const float* __restrict__ w1i,
                                                 const float* __restrict__ w2r, const float* __restrict__ w2i,
                                                 int layer) {
    __shared__ float2 Xs[16*64];
    __shared__ float2 Ws[64*64];
    int mode = blockIdx.x;
    int kx = mode >> 4, ky = mode & 15;
    int t = threadIdx.x;

    const float2* Xg = g_Xf + (size_t)mode * 1024;
    for (int j = t; j < 1024; j += 256) Xs[j] = Xg[j];

    const float* wr; const float* wi; int kxp;
    if (kx < 16) { wr = w1r; wi = w1i; kxp = kx; }
    else         { wr = w2r; wi = w2i; kxp = kx - 16; }
    size_t base = (size_t)layer * (NWID*NWID*256) + (size_t)kxp*16 + ky;
    for (int j = t; j < 4096; j += 256) {
        Ws[j] = make_float2(wr[base + (size_t)j*256], wi[base + (size_t)j*256]);
    }
    __syncthreads();

#pragma unroll
    for (int r = 0; r < 4; r++) {
        int oid = t + 256*r;
        int b = oid >> 6, o = oid & 63;
        float re = 0.f, im = 0.f;
#pragma unroll 8
        for (int i = 0; i < 64; i++) {
            float2 X = Xs[b*64 + i];
            float2 W = Ws[i*64 + o];
            re = fmaf(X.x, W.x, fmaf(-X.y, W.y, re));
            im = fmaf(X.x, W.y, fmaf( X.y, W.x, im));
        }
        g_Xo[((size_t)(b*64 + o)*16 + ky)*32 + kx] = make_float2(re, im);
    }
}

// ---------------- inverse DFT over H ----------------
__global__ __launch_bounds__(256) void k_idfth() {
    __shared__ float2 Xs[16*32];
    int bo = blockIdx.x;
    int t = threadIdx.x;
    {
        const float4* Xg4 = (const float4*)(g_Xo + (size_t)bo * 512);
        float4* Xs4 = (float4*)Xs;
        for (int j = t; j < 256; j += 256) Xs4[j] = Xg4[j];
    }
    __syncthreads();

    float cth[32], sth[32];
#pragma unroll
    for (int k = 0; k < 32; k++) { cth[k] = g_ch[k*256 + t]; sth[k] = g_sh[k*256 + t]; }

    const float scale = 1.0f / 65536.0f;
#pragma unroll 2
    for (int ky = 0; ky < 16; ky++) {
        float re = 0.f, im = 0.f;
#pragma unroll
        for (int k = 0; k < 32; k++) {
            float2 X = Xs[ky*32 + k];
            re = fmaf(X.x, cth[k], fmaf(-X.y, sth[k], re));
            im = fmaf(X.x, sth[k], fmaf( X.y, cth[k], im));
        }
        g_Z[((size_t)bo*256 + t)*16 + ky] = make_float2(re*scale, im*scale);
    }
}

// ---------------- k_final (layers 0-2): tf32 MMA GEMM + gelu ----------------
#define KF_SMEM_BYTES ((96*136 + 96*72 + 64) * 4)
__global__ __launch_bounds__(256) void k_final(int srcsel,
                                               const float* __restrict__ pw_w,
                                               const float* __restrict__ pw_b,
                                               int layer) {
    const float* __restrict__ hin  = srcsel ? g_h1 : g_h0;
    float*       __restrict__ hout = srcsel ? g_h0 : g_h1;

    extern __shared__ uint smem_u[];
    uint*  As  = smem_u;                       // [k][w] stride 136
    uint*  Bs  = smem_u + 96*136;              // [k][o] stride 72
    float* pbs = (float*)(smem_u + 96*136 + 96*72);

    int t = threadIdx.x;
    int lane = t & 31, warp = t >> 5;
    int bx = blockIdx.x;                       // 8192
    int b = bx >> 9, p = (bx >> 1) & 255, half = bx & 1;
    int w0 = half * 128;

    const float* hsrc = hin + (size_t)(b*64)*NPIX + (size_t)p*256 + w0;
#pragma unroll
    for (int rr = 0; rr < 8; rr++) {
        int i = warp*8 + rr;
        float4 v = *(const float4*)(hsrc + (size_t)i*NPIX + lane*4);
        uint4 uv = make_uint4(tf32u(v.x), tf32u(v.y), tf32u(v.z), tf32u(v.w));
        *(uint4*)(As + i*136 + lane*4) = uv;
    }
#pragma unroll
    for (int rep = 0; rep < 16; rep++) {
        int j = rep*256 + t;
        int e = j >> 7, w = j & 127;
        int q = e >> 1;
        float v = (e & 1) ? -g_sw[q*256 + w0 + w] : g_cw[q*256 + w0 + w];
        As[(64 + e)*136 + w] = tf32u(v);
    }
    const float* pwg = pw_w + (size_t)layer * 4096;
#pragma unroll
    for (int rep = 0; rep < 16; rep++) {
        int j = rep*256 + t;
        int o = j >> 6, i = j & 63;
        Bs[i*72 + o] = tf32u(pwg[j]);
    }
#pragma unroll
    for (int rep = 0; rep < 4; rep++) {
        int j = rep*256 + t;
        int o = j >> 4, q = j & 15;
        float2 z = g_Z[((size_t)(b*64 + o)*256 + p)*16 + q];
        float a = q ? 2.f : 1.f;
        Bs[(64 + 2*q    )*72 + o] = tf32u(a * z.x);
        Bs[(64 + 2*q + 1)*72 + o] = tf32u(a * z.y);
    }
    if (t < 64) pbs[t] = pw_b[layer*64 + t];
    __syncthreads();

    int warpM = warp & 3, warpN = warp >> 2;
    int m0 = warpM * 32, n0 = warpN * 32;
    int gr = lane >> 2, gc = lane & 3;

    float acc[2][4][4];
#pragma unroll
    for (int mi = 0; mi < 2; mi++)
#pragma unroll
        for (int ni = 0; ni < 4; ni++)
#pragma unroll
            for (int e = 0; e < 4; e++) acc[mi][ni][e] = 0.f;

#pragma unroll
    for (int ks = 0; ks < 12; ks++) {
        int k0 = ks * 8;
        uint a[2][4];
#pragma unroll
        for (int mi = 0; mi < 2; mi++) {
            int r = m0 + mi*16 + gr;
            a[mi][0] = As[(k0 + gc    )*136 + r];
            a[mi][1] = As[(k0 + gc    )*136 + r + 8];
            a[mi][2] = As[(k0 + gc + 4)*136 + r];
            a[mi][3] = As[(k0 + gc + 4)*136 + r + 8];
        }
        uint bf[4][2];
#pragma unroll
        for (int ni = 0; ni < 4; ni++) {
            int n = n0 + ni*8 + gr;
            bf[ni][0] = Bs[(k0 + gc    )*72 + n];
            bf[ni][1] = Bs[(k0 + gc + 4)*72 + n];
        }
#pragma unroll
        for (int mi = 0; mi < 2; mi++)
#pragma unroll
            for (int ni = 0; ni < 4; ni++)
                MMA_TF32(acc[mi][ni], a[mi], bf[ni]);
    }

    size_t outbase = (size_t)(b*64)*NPIX + (size_t)p*256 + w0;
#pragma unroll
    for (int mi = 0; mi < 2; mi++)
#pragma unroll
        for (int ni = 0; ni < 4; ni++)
#pragma unroll
            for (int e = 0; e < 4; e++) {
                int row = m0 + mi*16 + gr + (e >> 1)*8;
                int col = n0 + ni*8 + 2*gc + (e & 1);
                float val = gelu_f(acc[mi][ni][e] + pbs[col]);
                hout[outbase + (size_t)col*NPIX + row] = val;
            }
}

// ---------------- FUSED layer-3 k_final + fc1 + GELU + fc2 ----------------
// Phase 1: h3[w128][o64] = [hin|E][w][k96] x [pw;Z][k][o] + bias (tf32, no gelu)
// Phase 2: u[w][j128] = h3 x fc1w^T; GELU     Phase 3: out[w][o20] = u x fc2w^T
// smem layout (uints):
//   phase1: As[96*136) @0, Bs[96*72) @13056..19968
//   phase2: Hs(h3)[64*136) @0..8704, Bs1[64*136) @8704..17408
//   phase3: Hs2[128*136) @0..17408, Bs2[128*40) @17408..22528
//   pbs @22528(64) | b1s @22592(128) | b2s @22720(32)   total 22752 uints
#define KF3_SMEM_BYTES (22752 * 4)
__global__ __launch_bounds__(256) void k_f3fc(const float* __restrict__ pw_w,
                                              const float* __restrict__ pw_b,
                                              const float* __restrict__ fc1w, const float* __restrict__ fc1b,
                                              const float* __restrict__ fc2w, const float* __restrict__ fc2b,
                                              float* __restrict__ out) {
    const float* __restrict__ hin = g_h1;      // layer 3 reads h1

    extern __shared__ uint sm[];
    uint*  As  = sm;                           // phase1 [k][w] stride 136
    uint*  Bs  = sm + 96*136;                  // phase1 [k][o] stride 72
    uint*  Hs  = sm;                           // phase2 h3 [i][w] stride 136
    uint*  Bs1 = sm + 64*136;                  // phase2 fc1w [i][j] stride 136
    uint*  Hs2 = sm;                           // phase3 [j][w] stride 136 (overlaps Hs+Bs1)
    uint*  Bs2 = sm + 128*136;                 // phase3 fc2w [j][o] stride 40
    float* pbs = (float*)(sm + 22528);
    float* b1s = (float*)(sm + 22592);
    float* b2s = (float*)(sm + 22720);

    int t = threadIdx.x;
    int lane = t & 31, warp = t >> 5;
    int gr = lane >> 2, gc = lane & 3;
    int bx = blockIdx.x;                       // 8192 = b*512 + p*2 + half
    int b = bx >> 9, p = (bx >> 1) & 255, half = bx & 1;
    int w0 = half * 128;

    // ---- phase 1 staging (identical to k_final) ----
    const float* hsrc = hin + (size_t)(b*64)*NPIX + (size_t)p*256 + w0;
#pragma unroll
    for (int rr = 0; rr < 8; rr++) {
        int i = warp*8 + rr;
        float4 v = *(const float4*)(hsrc + (size_t)i*NPIX + lane*4);
        uint4 uv = make_uint4(tf32u(v.x), tf32u(v.y), tf32u(v.z), tf32u(v.w));
        *(uint4*)(As + i*136 + lane*4) = uv;
    }
#pragma unroll
    for (int rep = 0; rep < 16; rep++) {
        int j = rep*256 + t;
        int e = j >> 7, w = j & 127;
        int q = e >> 1;
        float v = (e & 1) ? -g_sw[q*256 + w0 + w] : g_cw[q*256 + w0 + w];
        As[(64 + e)*136 + w] = tf32u(v);
    }
    const float* pwg = pw_w + (size_t)3 * 4096;
#pragma unroll
    for (int rep = 0; rep < 16; rep++) {
        int j = rep*256 + t;
        int o = j >> 6, i = j & 63;
        Bs[i*72 + o] = tf32u(pwg[j]);
    }
#pragma unroll
    for (int rep = 0; rep < 4; rep++) {
        int j = rep*256 + t;
        int o = j >> 4, q = j & 15;
        float2 z = g_Z[((size_t)(b*64 + o)*256 + p)*16 + q];
        float a = q ? 2.f : 1.f;
        Bs[(64 + 2*q    )*72 + o] = tf32u(a * z.x);
        Bs[(64 + 2*q + 1)*72 + o] = tf32u(a * z.y);
    }
    if (t < 64)  pbs[t] = pw_b[3*64 + t];
    if (t < FCH) b1s[t] = fc1b[t];
    if (t < NCOUT) b2s[t] = fc2b[t];
    __syncthreads();

    // ---- phase 1 GEMM: h3 ----
    int warpM = warp & 3, warpN = warp >> 2;
    int m0 = warpM * 32, n0 = warpN * 32;

    float acc[2][4][4];
#pragma unroll
    for (int mi = 0; mi < 2; mi++)
#pragma unroll
        for (int ni = 0; ni < 4; ni++)
#pragma unroll
            for (int e = 0; e < 4; e++) acc[mi][ni][e] = 0.f;

#pragma unroll
    for (int ks = 0; ks < 12; ks++) {
        int k0 = ks * 8;
        uint a[2][4];
#pragma unroll
        for (int mi = 0; mi < 2; mi++) {
            int r = m0 + mi*16 + gr;
            a[mi][0] = As[(k0 + gc    )*136 + r];
            a[mi][1] = As[(k0 + gc    )*136 + r + 8];
            a[mi][2] = As[(k0 + gc + 4)*136 + r];
            a[mi][3] = As[(k0 + gc + 4)*136 + r + 8];
        }
        uint bf[4][2];
#pragma unroll
        for (int ni = 0; ni < 4; ni++) {
            int n = n0 + ni*8 + gr;
            bf[ni][0] = Bs[(k0 + gc    )*72 + n];
            bf[ni][1] = Bs[(k0 + gc + 4)*72 + n];
        }
#pragma unroll
        for (int mi = 0; mi < 2; mi++)
#pragma unroll
            for (int ni = 0; ni < 4; ni++)
                MMA_TF32(acc[mi][ni], a[mi], bf[ni]);
    }
    __syncthreads();   // As/Bs dead

    // ---- handoff: h3 -> Hs[i][w] tf32; stage fc1w/fc2w ----
#pragma unroll
    for (int mi = 0; mi < 2; mi++)
#pragma unroll
        for (int ni = 0; ni < 4; ni++)
#pragma unroll
            for (int e = 0; e < 4; e++) {
                int row = m0 + mi*16 + gr + (e >> 1)*8;      // w
                int col = n0 + ni*8 + 2*gc + (e & 1);        // o = i
                Hs[col*136 + row] = tf32u(acc[mi][ni][e] + pbs[col]);
            }
#pragma unroll
    for (int rep = 0; rep < 32; rep++) {
        int j2 = rep*256 + t;                  // 8192 = j*64 + i
        int jj = j2 >> 6, i = j2 & 63;
        Bs1[i*136 + jj] = tf32u(fc1w[j2]);
    }
#pragma unroll
    for (int rep = 0; rep < 12; rep++) {
        int j2 = rep*256 + t;                  // 3072 = jj*24 + o
        int jj = j2 / 24, o = j2 - jj*24;
        float v = (o < 20) ? fc2w[o*FCH + jj] : 0.f;
        Bs2[jj*40 + o] = tf32u(v);
    }
    __syncthreads();

    // ---- phase 2 GEMM: fc1 ----
    int warpM2 = warp & 1, warpN2 = warp >> 1;
    int m02 = warpM2 * 64, n02 = warpN2 * 32;
    float acc1[4][4][4];
#pragma unroll
    for (int mi = 0; mi < 4; mi++)
#pragma unroll
        for (int ni = 0; ni < 4; ni++)
#pragma unroll
            for (int e = 0; e < 4; e++) acc1[mi][ni][e] = 0.f;

#pragma unroll
    for (int ks = 0; ks < 8; ks++) {
        int k0 = ks * 8;
        uint a[4][4];
#pragma unroll
        for (int mi = 0; mi < 4; mi++) {
            int r = m02 + mi*16 + gr;
            a[mi][0] = Hs[(k0 + gc    )*136 + r];
            a[mi][1] = Hs[(k0 + gc    )*136 + r + 8];
            a[mi][2] = Hs[(k0 + gc + 4)*136 + r];
            a[mi][3] = Hs[(k0 + gc + 4)*136 + r + 8];
        }
        uint bf[4][2];
#pragma unroll
        for (int ni = 0; ni < 4; ni++) {
            int n = n02 + ni*8 + gr;
            bf[ni][0] = Bs1[(k0 + gc    )*136 + n];
            bf[ni][1] = Bs1[(k0 + gc + 4)*136 + n];
        }
#pragma unroll
        for (int mi = 0; mi < 4; mi++)
#pragma unroll
            for (int ni = 0; ni < 4; ni++)
                MMA_TF32(acc1[mi][ni], a[mi], bf[ni]);
    }
    __syncthreads();   // Hs/Bs1 dead

    // ---- GELU -> Hs2[j][w] ----
#pragma unroll
    for (int mi = 0; mi < 4; mi++)
#pragma unroll
        for (int ni = 0; ni < 4; ni++)
#pragma unroll
            for (int e = 0; e < 4; e++) {
                int row = m02 + mi*16 + gr + (e >> 1)*8;
                int col = n02 + ni*8 + 2*gc + (e & 1);
                float v = gelu_f(acc1[mi][ni][e] + b1s[col]);
                Hs2[col*136 + row] = tf32u(v);
            }
    __syncthreads();

    // ---- phase 3 GEMM: fc2 ----
    int m0b = warp * 16;
    float acc2[3][4];
#pragma unroll
    for (int ni = 0; ni < 3; ni++)
#pragma unroll
        for (int e = 0; e < 4; e++) acc2[ni][e] = 0.f;

#pragma unroll
    for (int ks = 0; ks < 16; ks++) {
        int k0 = ks * 8;
        uint a[4];
        {
            int r = m0b + gr;
            a[0] = Hs2[(k0 + gc    )*136 + r];
            a[1] = Hs2[(k0 + gc    )*136 + r + 8];
            a[2] = Hs2[(k0 + gc + 4)*136 + r];
            a[3] = Hs2[(k0 + gc + 4)*136 + r + 8];
        }
        uint bf[3][2];
#pragma unroll
        for (int ni = 0; ni < 3; ni++) {
            int n = ni*8 + gr;
            bf[ni][0] = Bs2[(k0 + gc    )*40 + n];
            bf[ni][1] = Bs2[(k0 + gc + 4)*40 + n];
        }
#pragma unroll
        for (int ni = 0; ni < 3; ni++)
            MMA_TF32(acc2[ni], a, bf[ni]);
    }

    size_t outbase = (size_t)(b*NCOUT)*NPIX + (size_t)p*256 + w0;
#pragma unroll
    for (int ni = 0; ni < 3; ni++)
#pragma unroll
        for (int e = 0; e < 4; e++) {
            int row = m0b + gr + (e >> 1)*8;
            int col = ni*8 + 2*gc + (e & 1);
            if (col < NCOUT)
                out[outbase + (size_t)col*NPIX + row] = acc2[ni][e] + b2s[col];
        }
}

// ---------------- launch ----------------
extern "C" void kernel_launch(void* const* d_in, const int* in_sizes, int n_in,
                              void* d_out, int out_size) {
    const float* x    = (const float*)d_in[0];
    const float* w1r  = (const float*)d_in[1];
    const float* w1i  = (const float*)d_in[2];
    const float* w2r  = (const float*)d_in[3];
    const float* w2i  = (const float*)d_in[4];
    const float* pw_w = (const float*)d_in[5];
    const float* pw_b = (const float*)d_in[6];
    const float* fc0w = (const float*)d_in[7];
    const float* fc0b = (const float*)d_in[8];
    const float* fc1w = (const float*)d_in[9];
    const float* fc1b = (const float*)d_in[10];
    const float* fc2w = (const float*)d_in[11];
    const float* fc2b = (const float*)d_in[12];
    float* out = (float*)d_out;

    cudaFuncSetAttribute(k_final, cudaFuncAttributeMaxDynamicSharedMemorySize, KF_SMEM_BYTES);
    cudaFuncSetAttribute(k_f3fc,  cudaFuncAttributeMaxDynamicSharedMemorySize, KF3_SMEM_BYTES);
    cudaFuncSetAttribute(k_dftw,  cudaFuncAttributeMaxDynamicSharedMemorySize, DFTW_SMEM);

    k_init_tables<<<32, 256>>>();
    k_fc0<<<4096, 256>>>(x, fc0w, fc0b);

    for (int l = 0; l < 3; l++) {
        int src = l & 1;                       // 0: read h0/write h1; 1: reverse
        k_dftw<<<4096, 256, DFTW_SMEM>>>(src);
        k_dfth<<<1024, 256>>>();
        k_modemix<<<512, 256>>>(w1r, w1i, w2r, w2i, l);
        k_idfth<<<1024, 256>>>();
        k_final<<<8192, 256, KF_SMEM_BYTES>>>(src, pw_w, pw_b, l);
    }
    // layer 3: dft stages read h1 (src=1), then fused final+projection
    k_dftw<<<4096, 256, DFTW_SMEM>>>(1);
    k_dfth<<<1024, 256>>>();
    k_modemix<<<512, 256>>>(w1r, w1i, w2r, w2i, 3);
    k_idfth<<<1024, 256>>>();
    k_f3fc<<<8192, 256, KF3_SMEM_BYTES>>>(pw_w, pw_b, fc1w, fc1b, fc2w, fc2b, out);
}